// round 3
// baseline (speedup 1.0000x reference)
#include <cuda_runtime.h>
#include <math.h>
#include <stdint.h>

// ---------------- problem constants ----------------
#define S_LEN   2048
#define HID     4096
#define QKV_N   12288
#define D_HEAD  128
#define HP_N    16
#define LAMBDA_INIT 0.35550906759096926f   // 0.8 - 0.6*exp(-0.3)
#define EPS     1e-5f

// ---------------- scratch (no allocations allowed) ----------------
__device__ float g_qkv[(size_t)S_LEN * QKV_N];   // 100.7 MB
__device__ float g_attn1[(size_t)S_LEN * HID];   // 33.5 MB
__device__ float g_attn2[(size_t)S_LEN * HID];   // 33.5 MB
__device__ float g_x[(size_t)S_LEN * HID];       // 33.5 MB
__device__ float g_lambda;

// ---------------- tf32 helpers ----------------
__device__ __forceinline__ uint32_t f2tf32(float f) {
    uint32_t o;
    asm("cvt.rna.tf32.f32 %0, %1;" : "=r"(o) : "f"(f));
    return o;
}

__device__ __forceinline__ void mma_tf32(float4& d,
                                         const uint32_t a0, const uint32_t a1,
                                         const uint32_t a2, const uint32_t a3,
                                         const uint32_t b0, const uint32_t b1)
{
    asm volatile(
        "mma.sync.aligned.m16n8k8.row.col.f32.tf32.tf32.f32 "
        "{%0,%1,%2,%3}, {%4,%5,%6,%7}, {%8,%9}, {%0,%1,%2,%3};\n"
        : "+f"(d.x), "+f"(d.y), "+f"(d.z), "+f"(d.w)
        : "r"(a0), "r"(a1), "r"(a2), "r"(a3), "r"(b0), "r"(b1));
}

// ---------------- tensor-core GEMM (tf32): C[M,N] = A[M,K] B[N,K]^T + bias ----
// block tile 128x128x32, 256 threads = 8 warps (2 m x 4 n), warp tile 64x32.
__global__ __launch_bounds__(256)
void sgemm_tc(const float* __restrict__ A, const float* __restrict__ B,
              const float* __restrict__ bias, float* __restrict__ C,
              int M, int N, int K)
{
    __shared__ uint32_t As[128][36];   // [m][k], tf32 bits, pad 4
    __shared__ uint32_t Bs[128][36];   // [n][k]

    const int tid  = threadIdx.x;
    const int wid  = tid >> 5;
    const int lane = tid & 31;
    const int wm   = (wid & 1) * 64;        // warp m offset in tile
    const int wn   = (wid >> 1) * 32;       // warp n offset in tile
    const int lr   = lane >> 2;             // 0..7
    const int lc   = lane & 3;              // 0..3

    const int m_blk = blockIdx.y * 128;
    const int n_blk = blockIdx.x * 128;

    // gmem load mapping: 1024 float4 per tile side, 4 per thread
    const int gRow = tid >> 1;                // 0..127
    const int gK0  = (tid & 1) * 16;          // 0 or 16

    float4 acc[4][4];
#pragma unroll
    for (int i = 0; i < 4; i++)
#pragma unroll
        for (int j = 0; j < 4; j++) acc[i][j] = make_float4(0.f, 0.f, 0.f, 0.f);

    const float* Ag = A + (size_t)(m_blk + gRow) * K + gK0;
    const float* Bg = B + (size_t)(n_blk + gRow) * K + gK0;

    for (int kt = 0; kt < K; kt += 32) {
        // global -> shared (convert to tf32 bits)
#pragma unroll
        for (int p = 0; p < 4; p++) {
            float4 av = *(const float4*)(Ag + kt + p * 4);
            float4 bv = *(const float4*)(Bg + kt + p * 4);
            int k = gK0 + p * 4;
            As[gRow][k + 0] = f2tf32(av.x); As[gRow][k + 1] = f2tf32(av.y);
            As[gRow][k + 2] = f2tf32(av.z); As[gRow][k + 3] = f2tf32(av.w);
            Bs[gRow][k + 0] = f2tf32(bv.x); Bs[gRow][k + 1] = f2tf32(bv.y);
            Bs[gRow][k + 2] = f2tf32(bv.z); Bs[gRow][k + 3] = f2tf32(bv.w);
        }
        __syncthreads();

#pragma unroll
        for (int ks = 0; ks < 4; ks++) {
            const int k0 = ks * 8;
            uint32_t af[4][4], bf[4][2];
#pragma unroll
            for (int im = 0; im < 4; im++) {
                const int r = wm + im * 16 + lr;
                af[im][0] = As[r    ][k0 + lc];
                af[im][1] = As[r + 8][k0 + lc];
                af[im][2] = As[r    ][k0 + lc + 4];
                af[im][3] = As[r + 8][k0 + lc + 4];
            }
#pragma unroll
            for (int in = 0; in < 4; in++) {
                const int n = wn + in * 8 + lr;
                bf[in][0] = Bs[n][k0 + lc];
                bf[in][1] = Bs[n][k0 + lc + 4];
            }
#pragma unroll
            for (int im = 0; im < 4; im++)
#pragma unroll
                for (int in = 0; in < 4; in++)
                    mma_tf32(acc[im][in], af[im][0], af[im][1], af[im][2], af[im][3],
                             bf[in][0], bf[in][1]);
        }
        __syncthreads();
    }

    // epilogue: D fragment mapping c0,c1 -> (row=lr, col=2*lc), c2,c3 -> row+8
#pragma unroll
    for (int im = 0; im < 4; im++) {
        const int r0 = m_blk + wm + im * 16 + lr;
#pragma unroll
        for (int in = 0; in < 4; in++) {
            const int c0 = n_blk + wn + in * 8 + 2 * lc;
            float2 bia = *(const float2*)&bias[c0];
            float* Cp0 = C + (size_t)r0 * N + c0;
            float* Cp1 = C + (size_t)(r0 + 8) * N + c0;
            Cp0[0] = acc[im][in].x + bia.x;
            Cp0[1] = acc[im][in].y + bia.y;
            Cp1[0] = acc[im][in].z + bia.x;
            Cp1[1] = acc[im][in].w + bia.y;
        }
    }
}

// ---------------- lambda scalar ----------------
__global__ void lambda_kernel(const float* __restrict__ q1, const float* __restrict__ k1,
                              const float* __restrict__ q2, const float* __restrict__ k2)
{
    const int tid = threadIdx.x;   // 128 threads
    float p1 = q1[tid] * k1[tid];
    float p2 = q2[tid] * k2[tid];
#pragma unroll
    for (int m = 16; m; m >>= 1) {
        p1 += __shfl_xor_sync(0xffffffffu, p1, m);
        p2 += __shfl_xor_sync(0xffffffffu, p2, m);
    }
    __shared__ float s1[4], s2[4];
    if ((tid & 31) == 0) { s1[tid >> 5] = p1; s2[tid >> 5] = p2; }
    __syncthreads();
    if (tid == 0) {
        float a = s1[0] + s1[1] + s1[2] + s1[3];
        float b = s2[0] + s2[1] + s2[2] + s2[3];
        g_lambda = expf(a) - expf(b) + LAMBDA_INIT;
    }
}

// ---------------- causal flash attention (fp32) ----------------
__global__ __launch_bounds__(256)
void diff_attn(const float* __restrict__ qkv,
               float* __restrict__ out1, float* __restrict__ out2)
{
    extern __shared__ float sm[];
    float* Qs   = sm;                 // [128][64]  d-major
    float* KV   = Qs + 128 * 64;      // K: [128][64] d-major, then V: [64][256]
    float* Ps   = KV + 64 * 256;      // [64][64]
    float* mrow = Ps + 64 * 64;       // [64]
    float* lrow = mrow + 64;          // [64]
    float* crow = lrow + 64;          // [64]
    float* tmax = crow + 64;          // [64]
    float* tsum = tmax + 64;          // [64]

    const int tid = threadIdx.x;
    const int qi  = blockIdx.x;
    const int hp  = blockIdx.y;
    const int a   = blockIdx.z;
    const int q0  = qi * 64;
    const int qoff = hp * 256 + a * 128;
    const int koff = HID + qoff;
    const int voff = 2 * HID + hp * 256;
    float* out = a ? out2 : out1;

    for (int i = tid; i < 64 * 32; i += 256) {
        int r = i >> 5; int d = (i & 31) << 2;
        float4 v = *(const float4*)&qkv[(size_t)(q0 + r) * QKV_N + qoff + d];
        Qs[(d + 0) * 64 + r] = v.x; Qs[(d + 1) * 64 + r] = v.y;
        Qs[(d + 2) * 64 + r] = v.z; Qs[(d + 3) * 64 + r] = v.w;
    }
    if (tid < 64) { mrow[tid] = -1e30f; lrow[tid] = 0.f; }

    const int tr = tid >> 4, tc = tid & 15;
    const int r0 = tr * 4, cs0 = tc * 4, cv0 = tc * 16;
    float oacc[4][16];
#pragma unroll
    for (int i = 0; i < 4; i++)
#pragma unroll
        for (int j = 0; j < 16; j++) oacc[i][j] = 0.f;
    __syncthreads();

    const float scale = 0.088388347648318447f;  // 1/sqrt(128)
    const int ntiles = qi + 1;

    for (int t = 0; t < ntiles; t++) {
        const int k0 = t * 64;

        for (int i = tid; i < 64 * 32; i += 256) {
            int c = i >> 5; int d = (i & 31) << 2;
            float4 v = *(const float4*)&qkv[(size_t)(k0 + c) * QKV_N + koff + d];
            KV[(d + 0) * 64 + c] = v.x; KV[(d + 1) * 64 + c] = v.y;
            KV[(d + 2) * 64 + c] = v.z; KV[(d + 3) * 64 + c] = v.w;
        }
        __syncthreads();

        float s4[4][4];
#pragma unroll
        for (int i = 0; i < 4; i++)
#pragma unroll
            for (int j = 0; j < 4; j++) s4[i][j] = 0.f;
#pragma unroll 4
        for (int d = 0; d < 128; d++) {
            float qa[4], kb[4];
            *(float4*)qa = *(const float4*)&Qs[d * 64 + r0];
            *(float4*)kb = *(const float4*)&KV[d * 64 + cs0];
#pragma unroll
            for (int i = 0; i < 4; i++)
#pragma unroll
                for (int j = 0; j < 4; j++)
                    s4[i][j] = fmaf(qa[i], kb[j], s4[i][j]);
        }
        __syncthreads();

        for (int i = tid; i < 64 * 64; i += 256) {
            int j = i >> 6; int e = (i & 63) << 2;
            *(float4*)&KV[j * 256 + e] =
                *(const float4*)&qkv[(size_t)(k0 + j) * QKV_N + voff + e];
        }

        const bool diag = (t == qi);
        float rm[4];
#pragma unroll
        for (int i = 0; i < 4; i++) {
            rm[i] = -1e30f;
#pragma unroll
            for (int j = 0; j < 4; j++) {
                float v = s4[i][j] * scale;
                if (diag && (k0 + cs0 + j) > (q0 + r0 + i)) v = -1e30f;
                s4[i][j] = v;
                rm[i] = fmaxf(rm[i], v);
            }
        }
#pragma unroll
        for (int m = 1; m < 16; m <<= 1)
#pragma unroll
            for (int i = 0; i < 4; i++)
                rm[i] = fmaxf(rm[i], __shfl_xor_sync(0xffffffffu, rm[i], m, 32));
        if (tc == 0) {
            tmax[r0 + 0] = rm[0]; tmax[r0 + 1] = rm[1];
            tmax[r0 + 2] = rm[2]; tmax[r0 + 3] = rm[3];
        }
        __syncthreads();

        if (tid < 64) {
            float mo = mrow[tid];
            float mn = fmaxf(mo, tmax[tid]);
            float c  = __expf(mo - mn);
            mrow[tid] = mn; crow[tid] = c; lrow[tid] *= c;
        }
        __syncthreads();

        float rs[4];
#pragma unroll
        for (int i = 0; i < 4; i++) {
            const float mn = mrow[r0 + i];
            rs[i] = 0.f;
#pragma unroll
            for (int j = 0; j < 4; j++) {
                float p = __expf(s4[i][j] - mn);
                Ps[(r0 + i) * 64 + cs0 + j] = p;
                rs[i] += p;
            }
            const float c = crow[r0 + i];
#pragma unroll
            for (int e = 0; e < 16; e++) oacc[i][e] *= c;
        }
#pragma unroll
        for (int m = 1; m < 16; m <<= 1)
#pragma unroll
            for (int i = 0; i < 4; i++)
                rs[i] += __shfl_xor_sync(0xffffffffu, rs[i], m, 32);
        if (tc == 0) {
            tsum[r0 + 0] = rs[0]; tsum[r0 + 1] = rs[1];
            tsum[r0 + 2] = rs[2]; tsum[r0 + 3] = rs[3];
        }
        __syncthreads();
        if (tid < 64) lrow[tid] += tsum[tid];

#pragma unroll 2
        for (int j = 0; j < 64; j++) {
            float p0 = Ps[(r0 + 0) * 64 + j];
            float p1 = Ps[(r0 + 1) * 64 + j];
            float p2 = Ps[(r0 + 2) * 64 + j];
            float p3 = Ps[(r0 + 3) * 64 + j];
            const float* vp = &KV[j * 256 + cv0];
#pragma unroll
            for (int e4 = 0; e4 < 4; e4++) {
                float4 vv = *(const float4*)&vp[e4 * 4];
                oacc[0][e4 * 4 + 0] = fmaf(p0, vv.x, oacc[0][e4 * 4 + 0]);
                oacc[0][e4 * 4 + 1] = fmaf(p0, vv.y, oacc[0][e4 * 4 + 1]);
                oacc[0][e4 * 4 + 2] = fmaf(p0, vv.z, oacc[0][e4 * 4 + 2]);
                oacc[0][e4 * 4 + 3] = fmaf(p0, vv.w, oacc[0][e4 * 4 + 3]);
                oacc[1][e4 * 4 + 0] = fmaf(p1, vv.x, oacc[1][e4 * 4 + 0]);
                oacc[1][e4 * 4 + 1] = fmaf(p1, vv.y, oacc[1][e4 * 4 + 1]);
                oacc[1][e4 * 4 + 2] = fmaf(p1, vv.z, oacc[1][e4 * 4 + 2]);
                oacc[1][e4 * 4 + 3] = fmaf(p1, vv.w, oacc[1][e4 * 4 + 3]);
                oacc[2][e4 * 4 + 0] = fmaf(p2, vv.x, oacc[2][e4 * 4 + 0]);
                oacc[2][e4 * 4 + 1] = fmaf(p2, vv.y, oacc[2][e4 * 4 + 1]);
                oacc[2][e4 * 4 + 2] = fmaf(p2, vv.z, oacc[2][e4 * 4 + 2]);
                oacc[2][e4 * 4 + 3] = fmaf(p2, vv.w, oacc[2][e4 * 4 + 3]);
                oacc[3][e4 * 4 + 0] = fmaf(p3, vv.x, oacc[3][e4 * 4 + 0]);
                oacc[3][e4 * 4 + 1] = fmaf(p3, vv.y, oacc[3][e4 * 4 + 1]);
                oacc[3][e4 * 4 + 2] = fmaf(p3, vv.z, oacc[3][e4 * 4 + 2]);
                oacc[3][e4 * 4 + 3] = fmaf(p3, vv.w, oacc[3][e4 * 4 + 3]);
            }
        }
        __syncthreads();
    }

#pragma unroll
    for (int i = 0; i < 4; i++) {
        const float inv = 1.f / lrow[r0 + i];
        float* op = out + (size_t)(q0 + r0 + i) * HID + hp * 256 + cv0;
#pragma unroll
        for (int e = 0; e < 16; e++) op[e] = oacc[i][e] * inv;
    }
}

// ---------------- combine (attn1 - lambda*attn2) + RMSNorm ----------------
__global__ __launch_bounds__(256)
void combine_rms(const float* __restrict__ a1, const float* __restrict__ a2,
                 const float* __restrict__ w, float* __restrict__ x)
{
    const int s = blockIdx.x, hp = blockIdx.y, e = threadIdx.x;
    const size_t idx = (size_t)s * HID + hp * 256 + e;
    const float lam = g_lambda;
    const float v = a1[idx] - lam * a2[idx];
    float ss = v * v;
#pragma unroll
    for (int m = 16; m; m >>= 1) ss += __shfl_xor_sync(0xffffffffu, ss, m);
    __shared__ float red[8];
    if ((e & 31) == 0) red[e >> 5] = ss;
    __syncthreads();
    float tot = 0.f;
#pragma unroll
    for (int i = 0; i < 8; i++) tot += red[i];
    const float r = rsqrtf(tot * (1.f / 256.f) + EPS);
    x[idx] = w[e] * v * r * (1.f - LAMBDA_INIT);
}

// ---------------- launch ----------------
extern "C" void kernel_launch(void* const* d_in, const int* in_sizes, int n_in,
                              void* d_out, int out_size)
{
    const float* hidden = (const float*)d_in[0];
    const float* Wqkv_w = (const float*)d_in[1];
    const float* Wqkv_b = (const float*)d_in[2];
    const float* out_w  = (const float*)d_in[3];
    const float* out_b  = (const float*)d_in[4];
    const float* lq1    = (const float*)d_in[5];
    const float* lk1    = (const float*)d_in[6];
    const float* lq2    = (const float*)d_in[7];
    const float* lk2    = (const float*)d_in[8];
    const float* subln  = (const float*)d_in[9];
    float* out = (float*)d_out;

    float *qkv, *a1, *a2, *x;
    cudaGetSymbolAddress((void**)&qkv, g_qkv);
    cudaGetSymbolAddress((void**)&a1,  g_attn1);
    cudaGetSymbolAddress((void**)&a2,  g_attn2);
    cudaGetSymbolAddress((void**)&x,   g_x);

    const int SMEM_ATT = (128 * 64 + 64 * 256 + 64 * 64 + 5 * 64) * (int)sizeof(float);
    cudaFuncSetAttribute(diff_attn, cudaFuncAttributeMaxDynamicSharedMemorySize, SMEM_ATT);

    // 1. lambda scalar
    lambda_kernel<<<1, 128>>>(lq1, lk1, lq2, lk2);

    // 2. QKV projection (tensor cores, tf32)
    sgemm_tc<<<dim3(QKV_N / 128, S_LEN / 128), 256>>>(
        hidden, Wqkv_w, Wqkv_b, qkv, S_LEN, QKV_N, HID);

    // 3. dual causal flash attention
    diff_attn<<<dim3(S_LEN / 64, HP_N, 2), 256, SMEM_ATT>>>(qkv, a1, a2);

    // 4. combine + rmsnorm
    combine_rms<<<dim3(S_LEN, HP_N), 256>>>(a1, a2, subln, x);

    // 5. output projection (tensor cores, tf32)
    sgemm_tc<<<dim3(HID / 128, S_LEN / 128), 256>>>(
        x, out_w, out_b, out, S_LEN, HID, HID);
}

// round 4
// speedup vs baseline: 1.6859x; 1.6859x over previous
#include <cuda_runtime.h>
#include <math.h>
#include <stdint.h>

// ---------------- problem constants ----------------
#define S_LEN   2048
#define HID     4096
#define QKV_N   12288
#define HP_N    16
#define LAMBDA_INIT 0.35550906759096926f
#define EPS     1e-5f
#define SCALE   0.088388347648318447f   // 1/sqrt(128)

// ---------------- scratch ----------------
__device__ float g_qkv[(size_t)S_LEN * QKV_N];
__device__ float g_attn1[(size_t)S_LEN * HID];
__device__ float g_attn2[(size_t)S_LEN * HID];
__device__ float g_x[(size_t)S_LEN * HID];
__device__ float g_lambda;

// ---------------- tf32 helpers (GEMM) ----------------
__device__ __forceinline__ uint32_t f2tf32(float f) {
    uint32_t o; asm("cvt.rna.tf32.f32 %0, %1;" : "=r"(o) : "f"(f)); return o;
}
__device__ __forceinline__ void mma_tf32(float4& d,
    uint32_t a0, uint32_t a1, uint32_t a2, uint32_t a3, uint32_t b0, uint32_t b1)
{
    asm volatile("mma.sync.aligned.m16n8k8.row.col.f32.tf32.tf32.f32 "
        "{%0,%1,%2,%3}, {%4,%5,%6,%7}, {%8,%9}, {%0,%1,%2,%3};\n"
        : "+f"(d.x), "+f"(d.y), "+f"(d.z), "+f"(d.w)
        : "r"(a0), "r"(a1), "r"(a2), "r"(a3), "r"(b0), "r"(b1));
}

// ---------------- bf16 helpers (attention) ----------------
__device__ __forceinline__ void mma_bf16(float* d,
    uint32_t a0, uint32_t a1, uint32_t a2, uint32_t a3, uint32_t b0, uint32_t b1)
{
    asm volatile("mma.sync.aligned.m16n8k16.row.col.f32.bf16.bf16.f32 "
        "{%0,%1,%2,%3}, {%4,%5,%6,%7}, {%8,%9}, {%0,%1,%2,%3};\n"
        : "+f"(d[0]), "+f"(d[1]), "+f"(d[2]), "+f"(d[3])
        : "r"(a0), "r"(a1), "r"(a2), "r"(a3), "r"(b0), "r"(b1));
}
__device__ __forceinline__ void ldsm4(uint32_t* r, uint32_t a) {
    asm volatile("ldmatrix.sync.aligned.m8n8.x4.shared.b16 {%0,%1,%2,%3}, [%4];"
        : "=r"(r[0]), "=r"(r[1]), "=r"(r[2]), "=r"(r[3]) : "r"(a));
}
__device__ __forceinline__ void ldsm4t(uint32_t* r, uint32_t a) {
    asm volatile("ldmatrix.sync.aligned.m8n8.x4.trans.shared.b16 {%0,%1,%2,%3}, [%4];"
        : "=r"(r[0]), "=r"(r[1]), "=r"(r[2]), "=r"(r[3]) : "r"(a));
}
// packed pair (low half = a): hi = truncate-to-bf16
__device__ __forceinline__ uint32_t pack_hi(float a, float b) {
    return __byte_perm(__float_as_uint(a), __float_as_uint(b), 0x7632);
}
// lo = rn-bf16 of residuals (low half = a's residual)
__device__ __forceinline__ uint32_t pack_lo(float a, float b) {
    float ra = a - __uint_as_float(__float_as_uint(a) & 0xffff0000u);
    float rb = b - __uint_as_float(__float_as_uint(b) & 0xffff0000u);
    uint32_t r;
    asm("cvt.rn.bf16x2.f32 %0, %1, %2;" : "=r"(r) : "f"(rb), "f"(ra));
    return r;
}

// ---------------- tensor-core GEMM (tf32): C = A B^T + bias ----------------
__global__ __launch_bounds__(256)
void sgemm_tc(const float* __restrict__ A, const float* __restrict__ B,
              const float* __restrict__ bias, float* __restrict__ C,
              int M, int N, int K)
{
    __shared__ uint32_t As[128][36];
    __shared__ uint32_t Bs[128][36];

    const int tid = threadIdx.x, wid = tid >> 5, lane = tid & 31;
    const int wm = (wid & 1) * 64, wn = (wid >> 1) * 32;
    const int lr = lane >> 2, lc = lane & 3;
    const int m_blk = blockIdx.y * 128, n_blk = blockIdx.x * 128;
    const int gRow = tid >> 1, gK0 = (tid & 1) * 16;

    float4 acc[4][4];
#pragma unroll
    for (int i = 0; i < 4; i++)
#pragma unroll
        for (int j = 0; j < 4; j++) acc[i][j] = make_float4(0.f, 0.f, 0.f, 0.f);

    const float* Ag = A + (size_t)(m_blk + gRow) * K + gK0;
    const float* Bg = B + (size_t)(n_blk + gRow) * K + gK0;

    for (int kt = 0; kt < K; kt += 32) {
#pragma unroll
        for (int p = 0; p < 4; p++) {
            float4 av = *(const float4*)(Ag + kt + p * 4);
            float4 bv = *(const float4*)(Bg + kt + p * 4);
            int k = gK0 + p * 4;
            As[gRow][k+0]=f2tf32(av.x); As[gRow][k+1]=f2tf32(av.y);
            As[gRow][k+2]=f2tf32(av.z); As[gRow][k+3]=f2tf32(av.w);
            Bs[gRow][k+0]=f2tf32(bv.x); Bs[gRow][k+1]=f2tf32(bv.y);
            Bs[gRow][k+2]=f2tf32(bv.z); Bs[gRow][k+3]=f2tf32(bv.w);
        }
        __syncthreads();
#pragma unroll
        for (int ks = 0; ks < 4; ks++) {
            const int k0 = ks * 8;
            uint32_t af[4][4], bf[4][2];
#pragma unroll
            for (int im = 0; im < 4; im++) {
                const int r = wm + im * 16 + lr;
                af[im][0]=As[r][k0+lc];   af[im][1]=As[r+8][k0+lc];
                af[im][2]=As[r][k0+lc+4]; af[im][3]=As[r+8][k0+lc+4];
            }
#pragma unroll
            for (int in = 0; in < 4; in++) {
                const int n = wn + in * 8 + lr;
                bf[in][0]=Bs[n][k0+lc]; bf[in][1]=Bs[n][k0+lc+4];
            }
#pragma unroll
            for (int im = 0; im < 4; im++)
#pragma unroll
                for (int in = 0; in < 4; in++)
                    mma_tf32(acc[im][in], af[im][0],af[im][1],af[im][2],af[im][3],
                             bf[in][0], bf[in][1]);
        }
        __syncthreads();
    }
#pragma unroll
    for (int im = 0; im < 4; im++) {
        const int r0 = m_blk + wm + im * 16 + lr;
#pragma unroll
        for (int in = 0; in < 4; in++) {
            const int c0 = n_blk + wn + in * 8 + 2 * lc;
            float2 bia = *(const float2*)&bias[c0];
            float* Cp0 = C + (size_t)r0 * N + c0;
            float* Cp1 = C + (size_t)(r0 + 8) * N + c0;
            Cp0[0]=acc[im][in].x+bia.x; Cp0[1]=acc[im][in].y+bia.y;
            Cp1[0]=acc[im][in].z+bia.x; Cp1[1]=acc[im][in].w+bia.y;
        }
    }
}

// ---------------- lambda scalar ----------------
__global__ void lambda_kernel(const float* __restrict__ q1, const float* __restrict__ k1,
                              const float* __restrict__ q2, const float* __restrict__ k2)
{
    const int tid = threadIdx.x;
    float p1 = q1[tid] * k1[tid];
    float p2 = q2[tid] * k2[tid];
#pragma unroll
    for (int m = 16; m; m >>= 1) {
        p1 += __shfl_xor_sync(0xffffffffu, p1, m);
        p2 += __shfl_xor_sync(0xffffffffu, p2, m);
    }
    __shared__ float s1[4], s2[4];
    if ((tid & 31) == 0) { s1[tid >> 5] = p1; s2[tid >> 5] = p2; }
    __syncthreads();
    if (tid == 0) {
        float a = s1[0]+s1[1]+s1[2]+s1[3];
        float b = s2[0]+s2[1]+s2[2]+s2[3];
        g_lambda = expf(a) - expf(b) + LAMBDA_INIT;
    }
}

// ---------------- bf16x3 tensor-core causal flash attention ----------------
// word strides (all ≡ 4 mod 32 -> conflict-free ldmatrix)
#define QH_W 68
#define VH_W 132
#define PH_W 36
#define QH_OFF 0
#define QL_OFF (QH_OFF + 64*QH_W)
#define KH_OFF (QL_OFF + 64*QH_W)
#define KL_OFF (KH_OFF + 64*QH_W)
#define VH_OFF (KL_OFF + 64*QH_W)
#define VL_OFF (VH_OFF + 64*VH_W)
#define PH_OFF (VL_OFF + 64*VH_W)
#define PL_OFF (PH_OFF + 64*PH_W)
#define ST_OFF (PL_OFF + 64*PH_W)
#define ATT_WORDS (ST_OFF + 64*7)

__global__ __launch_bounds__(256, 1)
void diff_attn(const float* __restrict__ qkv,
               float* __restrict__ out1, float* __restrict__ out2)
{
    extern __shared__ uint32_t sw[];
    float* mrow = (float*)(sw + ST_OFF);   // [64]
    float* crow = mrow + 64;               // [64]
    float* lrow = crow + 64;               // [64]
    float* pmax = lrow + 64;               // [2][64]
    float* psum = pmax + 128;              // [2][64]

    const int tid = threadIdx.x, lane = tid & 31, w = tid >> 5;
    const int qi = blockIdx.x, hp = blockIdx.y, aa = blockIdx.z;
    const int q0 = qi * 64;
    const size_t qoff = (size_t)hp * 256 + (size_t)aa * 128;
    const size_t koff = HID + qoff;
    const size_t voff = 2 * (size_t)HID + (size_t)hp * 256;
    float* outp = aa ? out2 : out1;
    const uint32_t smb = (uint32_t)__cvta_generic_to_shared(sw);

    // load Q (pre-scaled), split hi/lo
    {
        const int r = tid >> 2, c0 = (tid & 3) * 32;
        const float* src = qkv + (size_t)(q0 + r) * QKV_N + qoff + c0;
        const int wb = r * QH_W + c0 / 2;
#pragma unroll
        for (int i = 0; i < 8; i++) {
            float4 v = *(const float4*)(src + 4 * i);
            v.x *= SCALE; v.y *= SCALE; v.z *= SCALE; v.w *= SCALE;
            sw[QH_OFF + wb + 2*i]   = pack_hi(v.x, v.y);
            sw[QH_OFF + wb + 2*i+1] = pack_hi(v.z, v.w);
            sw[QL_OFF + wb + 2*i]   = pack_lo(v.x, v.y);
            sw[QL_OFF + wb + 2*i+1] = pack_lo(v.z, v.w);
        }
    }
    if (tid < 64) { mrow[tid] = -1e30f; lrow[tid] = 0.f; }

    const int wm  = (w & 3) * 16;     // m band
    const int nh2 = w >> 2;           // 0/1
    const int wn  = nh2 * 32;         // QK n offset
    const int en0 = nh2 * 128;        // PV e offset
    const int lq  = lane >> 2;        // 0..7
    const int lr4 = lane & 3;

    float o[16][4];
#pragma unroll
    for (int i = 0; i < 16; i++)
#pragma unroll
        for (int j = 0; j < 4; j++) o[i][j] = 0.f;

    for (int t = 0; t <= qi; t++) {
        const int k0g = t * 64;
        // --- load K (hi/lo) ---
        {
            const int r = tid >> 2, c0 = (tid & 3) * 32;
            const float* src = qkv + (size_t)(k0g + r) * QKV_N + koff + c0;
            const int wb = r * QH_W + c0 / 2;
#pragma unroll
            for (int i = 0; i < 8; i++) {
                float4 v = *(const float4*)(src + 4 * i);
                sw[KH_OFF + wb + 2*i]   = pack_hi(v.x, v.y);
                sw[KH_OFF + wb + 2*i+1] = pack_hi(v.z, v.w);
                sw[KL_OFF + wb + 2*i]   = pack_lo(v.x, v.y);
                sw[KL_OFF + wb + 2*i+1] = pack_lo(v.z, v.w);
            }
        }
        // --- load V (hi/lo) ---
        {
            const int r = tid >> 2, e0 = (tid & 3) * 64;
            const float* src = qkv + (size_t)(k0g + r) * QKV_N + voff + e0;
            const int wb = r * VH_W + e0 / 2;
#pragma unroll
            for (int i = 0; i < 16; i++) {
                float4 v = *(const float4*)(src + 4 * i);
                sw[VH_OFF + wb + 2*i]   = pack_hi(v.x, v.y);
                sw[VH_OFF + wb + 2*i+1] = pack_hi(v.z, v.w);
                sw[VL_OFF + wb + 2*i]   = pack_lo(v.x, v.y);
                sw[VL_OFF + wb + 2*i+1] = pack_lo(v.z, v.w);
            }
        }
        __syncthreads();

        // --- S = Q K^T (warp: 16 rows x 32 cols), bf16x3 ---
        float c4[4][4];
#pragma unroll
        for (int nt = 0; nt < 4; nt++)
#pragma unroll
            for (int j = 0; j < 4; j++) c4[nt][j] = 0.f;

#pragma unroll
        for (int ks = 0; ks < 8; ks++) {
            const uint32_t cb = ks * 32 + (lane >> 4) * 16;
            uint32_t qh[4], ql[4];
            ldsm4(qh, smb + ((QH_OFF + (wm + (lane & 15)) * QH_W) << 2) + cb);
            ldsm4(ql, smb + ((QL_OFF + (wm + (lane & 15)) * QH_W) << 2) + cb);
#pragma unroll
            for (int nh = 0; nh < 2; nh++) {
                const int krow = wn + nh * 16 + (lane & 15);
                uint32_t kh[4], kl[4];
                ldsm4(kh, smb + ((KH_OFF + krow * QH_W) << 2) + cb);
                ldsm4(kl, smb + ((KL_OFF + krow * QH_W) << 2) + cb);
#pragma unroll
                for (int g = 0; g < 2; g++) {
                    float* c = c4[nh * 2 + g];
                    mma_bf16(c, qh[0],qh[1],qh[2],qh[3], kh[g], kh[g+2]);
                    mma_bf16(c, qh[0],qh[1],qh[2],qh[3], kl[g], kl[g+2]);
                    mma_bf16(c, ql[0],ql[1],ql[2],ql[3], kh[g], kh[g+2]);
                }
            }
        }

        // --- mask + row max ---
        const bool diag = (t == qi);
        float m0 = -1e30f, m1 = -1e30f;
#pragma unroll
        for (int nt = 0; nt < 4; nt++) {
            if (diag) {
                const int kc = wn + nt * 8 + 2 * lr4;
                const int rr0 = wm + lq, rr1 = rr0 + 8;
                if (kc     > rr0) c4[nt][0] = -1e30f;
                if (kc + 1 > rr0) c4[nt][1] = -1e30f;
                if (kc     > rr1) c4[nt][2] = -1e30f;
                if (kc + 1 > rr1) c4[nt][3] = -1e30f;
            }
            m0 = fmaxf(m0, fmaxf(c4[nt][0], c4[nt][1]));
            m1 = fmaxf(m1, fmaxf(c4[nt][2], c4[nt][3]));
        }
        m0 = fmaxf(m0, __shfl_xor_sync(0xffffffffu, m0, 1));
        m0 = fmaxf(m0, __shfl_xor_sync(0xffffffffu, m0, 2));
        m1 = fmaxf(m1, __shfl_xor_sync(0xffffffffu, m1, 1));
        m1 = fmaxf(m1, __shfl_xor_sync(0xffffffffu, m1, 2));
        if (lr4 == 0) {
            pmax[nh2 * 64 + wm + lq]     = m0;
            pmax[nh2 * 64 + wm + lq + 8] = m1;
        }
        __syncthreads();

        if (tid < 64) {
            float mo = mrow[tid];
            float mn = fmaxf(mo, fmaxf(pmax[tid], pmax[64 + tid]));
            mrow[tid] = mn;
            crow[tid] = __expf(mo - mn);
        }
        __syncthreads();

        // --- P = exp(S - m) -> smem (hi/lo), row sums, O rescale ---
        const float mn0 = mrow[wm + lq], mn1 = mrow[wm + lq + 8];
        const float cr0 = crow[wm + lq], cr1 = crow[wm + lq + 8];
        float s0 = 0.f, s1 = 0.f;
#pragma unroll
        for (int nt = 0; nt < 4; nt++) {
            float p0 = __expf(c4[nt][0] - mn0);
            float p1 = __expf(c4[nt][1] - mn0);
            float p2 = __expf(c4[nt][2] - mn1);
            float p3 = __expf(c4[nt][3] - mn1);
            s0 += p0 + p1; s1 += p2 + p3;
            const int wc = wn / 2 + nt * 4 + lr4;
            sw[PH_OFF + (wm + lq) * PH_W + wc]     = pack_hi(p0, p1);
            sw[PL_OFF + (wm + lq) * PH_W + wc]     = pack_lo(p0, p1);
            sw[PH_OFF + (wm + lq + 8) * PH_W + wc] = pack_hi(p2, p3);
            sw[PL_OFF + (wm + lq + 8) * PH_W + wc] = pack_lo(p2, p3);
        }
        s0 += __shfl_xor_sync(0xffffffffu, s0, 1);
        s0 += __shfl_xor_sync(0xffffffffu, s0, 2);
        s1 += __shfl_xor_sync(0xffffffffu, s1, 1);
        s1 += __shfl_xor_sync(0xffffffffu, s1, 2);
        if (lr4 == 0) {
            psum[nh2 * 64 + wm + lq]     = s0;
            psum[nh2 * 64 + wm + lq + 8] = s1;
        }
#pragma unroll
        for (int nt = 0; nt < 16; nt++) {
            o[nt][0] *= cr0; o[nt][1] *= cr0;
            o[nt][2] *= cr1; o[nt][3] *= cr1;
        }
        __syncthreads();
        if (tid < 64) lrow[tid] = lrow[tid] * crow[tid] + psum[tid] + psum[64 + tid];

        // --- O += P V (warp: 16 rows x 128 e-cols), bf16x3 ---
#pragma unroll
        for (int ks = 0; ks < 4; ks++) {
            const uint32_t pcb = ks * 32 + (lane >> 4) * 16;
            uint32_t ph[4], pl[4];
            ldsm4(ph, smb + ((PH_OFF + (wm + (lane & 15)) * PH_W) << 2) + pcb);
            ldsm4(pl, smb + ((PL_OFF + (wm + (lane & 15)) * PH_W) << 2) + pcb);
            const int kvrow = ks * 16 + (lane & 15);
#pragma unroll
            for (int ec = 0; ec < 8; ec++) {
                const uint32_t vcb = (uint32_t)((en0 + ec * 16 + (lane >> 4) * 8) << 1);
                uint32_t vh[4], vl[4];
                ldsm4t(vh, smb + ((VH_OFF + kvrow * VH_W) << 2) + vcb);
                ldsm4t(vl, smb + ((VL_OFF + kvrow * VH_W) << 2) + vcb);
#pragma unroll
                for (int g = 0; g < 2; g++) {
                    float* oo = o[ec * 2 + g];
                    mma_bf16(oo, ph[0],ph[1],ph[2],ph[3], vh[2*g], vh[2*g+1]);
                    mma_bf16(oo, ph[0],ph[1],ph[2],ph[3], vl[2*g], vl[2*g+1]);
                    mma_bf16(oo, pl[0],pl[1],pl[2],pl[3], vh[2*g], vh[2*g+1]);
                }
            }
        }
        __syncthreads();
    }

    // --- epilogue ---
    const float inv0 = 1.f / lrow[wm + lq];
    const float inv1 = 1.f / lrow[wm + lq + 8];
    const size_t row0 = (size_t)q0 + wm + lq, row1 = row0 + 8;
#pragma unroll
    for (int nt = 0; nt < 16; nt++) {
        const int col = hp * 256 + en0 + nt * 8 + 2 * lr4;
        float2 v0 = make_float2(o[nt][0] * inv0, o[nt][1] * inv0);
        float2 v1 = make_float2(o[nt][2] * inv1, o[nt][3] * inv1);
        *(float2*)&outp[row0 * HID + col] = v0;
        *(float2*)&outp[row1 * HID + col] = v1;
    }
}

// ---------------- combine + RMSNorm ----------------
__global__ __launch_bounds__(256)
void combine_rms(const float* __restrict__ a1, const float* __restrict__ a2,
                 const float* __restrict__ w, float* __restrict__ x)
{
    const int s = blockIdx.x, hp = blockIdx.y, e = threadIdx.x;
    const size_t idx = (size_t)s * HID + hp * 256 + e;
    const float lam = g_lambda;
    const float v = a1[idx] - lam * a2[idx];
    float ss = v * v;
#pragma unroll
    for (int m = 16; m; m >>= 1) ss += __shfl_xor_sync(0xffffffffu, ss, m);
    __shared__ float red[8];
    if ((e & 31) == 0) red[e >> 5] = ss;
    __syncthreads();
    float tot = 0.f;
#pragma unroll
    for (int i = 0; i < 8; i++) tot += red[i];
    const float r = rsqrtf(tot * (1.f / 256.f) + EPS);
    x[idx] = w[e] * v * r * (1.f - LAMBDA_INIT);
}

// ---------------- launch ----------------
extern "C" void kernel_launch(void* const* d_in, const int* in_sizes, int n_in,
                              void* d_out, int out_size)
{
    const float* hidden = (const float*)d_in[0];
    const float* Wqkv_w = (const float*)d_in[1];
    const float* Wqkv_b = (const float*)d_in[2];
    const float* out_w  = (const float*)d_in[3];
    const float* out_b  = (const float*)d_in[4];
    const float* lq1    = (const float*)d_in[5];
    const float* lk1    = (const float*)d_in[6];
    const float* lq2    = (const float*)d_in[7];
    const float* lk2    = (const float*)d_in[8];
    const float* subln  = (const float*)d_in[9];
    float* out = (float*)d_out;

    float *qkv, *a1, *a2, *x;
    cudaGetSymbolAddress((void**)&qkv, g_qkv);
    cudaGetSymbolAddress((void**)&a1,  g_attn1);
    cudaGetSymbolAddress((void**)&a2,  g_attn2);
    cudaGetSymbolAddress((void**)&x,   g_x);

    const int SMEM_ATT = ATT_WORDS * (int)sizeof(uint32_t);
    cudaFuncSetAttribute(diff_attn, cudaFuncAttributeMaxDynamicSharedMemorySize, SMEM_ATT);

    lambda_kernel<<<1, 128>>>(lq1, lk1, lq2, lk2);

    sgemm_tc<<<dim3(QKV_N / 128, S_LEN / 128), 256>>>(
        hidden, Wqkv_w, Wqkv_b, qkv, S_LEN, QKV_N, HID);

    diff_attn<<<dim3(S_LEN / 64, HP_N, 2), 256, SMEM_ATT>>>(qkv, a1, a2);

    combine_rms<<<dim3(S_LEN, HP_N), 256>>>(a1, a2, subln, x);

    sgemm_tc<<<dim3(HID / 128, S_LEN / 128), 256>>>(
        x, out_w, out_b, out, S_LEN, HID, HID);
}

// round 5
// speedup vs baseline: 1.8206x; 1.0799x over previous
#include <cuda_runtime.h>
#include <math.h>
#include <stdint.h>

// ---------------- problem constants ----------------
#define S_LEN   2048
#define HID     4096
#define QKV_N   12288
#define HP_N    16
#define LAMBDA_INIT 0.35550906759096926f
#define EPS     1e-5f
#define SCALE   0.088388347648318447f   // 1/sqrt(128)
#define NW      (QKV_N / 2)             // qkv row width in bf16x2 words

// ---------------- scratch ----------------
__device__ uint32_t g_qkvh[(size_t)S_LEN * NW];   // bf16x2 hi words, 50MB
__device__ uint32_t g_qkvl[(size_t)S_LEN * NW];   // bf16x2 lo words, 50MB
__device__ float g_attn1[(size_t)S_LEN * HID];
__device__ float g_attn2[(size_t)S_LEN * HID];
__device__ float g_x[(size_t)S_LEN * HID];
__device__ float g_lambda;

// ---------------- tf32 helpers (GEMM) ----------------
__device__ __forceinline__ uint32_t f2tf32(float f) {
    uint32_t o; asm("cvt.rna.tf32.f32 %0, %1;" : "=r"(o) : "f"(f)); return o;
}
__device__ __forceinline__ void mma_tf32(float4& d,
    uint32_t a0, uint32_t a1, uint32_t a2, uint32_t a3, uint32_t b0, uint32_t b1)
{
    asm volatile("mma.sync.aligned.m16n8k8.row.col.f32.tf32.tf32.f32 "
        "{%0,%1,%2,%3}, {%4,%5,%6,%7}, {%8,%9}, {%0,%1,%2,%3};\n"
        : "+f"(d.x), "+f"(d.y), "+f"(d.z), "+f"(d.w)
        : "r"(a0), "r"(a1), "r"(a2), "r"(a3), "r"(b0), "r"(b1));
}

// ---------------- bf16 helpers ----------------
__device__ __forceinline__ void mma_bf16(float* d,
    uint32_t a0, uint32_t a1, uint32_t a2, uint32_t a3, uint32_t b0, uint32_t b1)
{
    asm volatile("mma.sync.aligned.m16n8k16.row.col.f32.bf16.bf16.f32 "
        "{%0,%1,%2,%3}, {%4,%5,%6,%7}, {%8,%9}, {%0,%1,%2,%3};\n"
        : "+f"(d[0]), "+f"(d[1]), "+f"(d[2]), "+f"(d[3])
        : "r"(a0), "r"(a1), "r"(a2), "r"(a3), "r"(b0), "r"(b1));
}
__device__ __forceinline__ void ldsm4(uint32_t* r, uint32_t a) {
    asm volatile("ldmatrix.sync.aligned.m8n8.x4.shared.b16 {%0,%1,%2,%3}, [%4];"
        : "=r"(r[0]), "=r"(r[1]), "=r"(r[2]), "=r"(r[3]) : "r"(a));
}
__device__ __forceinline__ void ldsm4t(uint32_t* r, uint32_t a) {
    asm volatile("ldmatrix.sync.aligned.m8n8.x4.trans.shared.b16 {%0,%1,%2,%3}, [%4];"
        : "=r"(r[0]), "=r"(r[1]), "=r"(r[2]), "=r"(r[3]) : "r"(a));
}
__device__ __forceinline__ uint32_t pack_hi(float a, float b) {
    return __byte_perm(__float_as_uint(a), __float_as_uint(b), 0x7632);
}
__device__ __forceinline__ uint32_t pack_lo(float a, float b) {
    float ra = a - __uint_as_float(__float_as_uint(a) & 0xffff0000u);
    float rb = b - __uint_as_float(__float_as_uint(b) & 0xffff0000u);
    uint32_t r;
    asm("cvt.rn.bf16x2.f32 %0, %1, %2;" : "=r"(r) : "f"(rb), "f"(ra));
    return r;
}
__device__ __forceinline__ void cpa16(uint32_t dst_b, const void* src) {
    asm volatile("cp.async.cg.shared.global [%0], [%1], 16;" :: "r"(dst_b), "l"(src));
}

// ---------------- tensor-core GEMM (tf32): C = A B^T + bias ----------------
// If Ch != null, write bf16 hi/lo split (Q columns pre-scaled) instead of fp32.
__global__ __launch_bounds__(256)
void sgemm_tc(const float* __restrict__ A, const float* __restrict__ B,
              const float* __restrict__ bias, float* __restrict__ C,
              uint32_t* __restrict__ Ch, uint32_t* __restrict__ Cl,
              int M, int N, int K)
{
    __shared__ uint32_t As[128][36];
    __shared__ uint32_t Bs[128][36];

    const int tid = threadIdx.x, wid = tid >> 5, lane = tid & 31;
    const int wm = (wid & 1) * 64, wn = (wid >> 1) * 32;
    const int lr = lane >> 2, lc = lane & 3;
    const int m_blk = blockIdx.y * 128, n_blk = blockIdx.x * 128;
    const int gRow = tid >> 1, gK0 = (tid & 1) * 16;

    float4 acc[4][4];
#pragma unroll
    for (int i = 0; i < 4; i++)
#pragma unroll
        for (int j = 0; j < 4; j++) acc[i][j] = make_float4(0.f, 0.f, 0.f, 0.f);

    const float* Ag = A + (size_t)(m_blk + gRow) * K + gK0;
    const float* Bg = B + (size_t)(n_blk + gRow) * K + gK0;

    for (int kt = 0; kt < K; kt += 32) {
#pragma unroll
        for (int p = 0; p < 4; p++) {
            float4 av = *(const float4*)(Ag + kt + p * 4);
            float4 bv = *(const float4*)(Bg + kt + p * 4);
            int k = gK0 + p * 4;
            As[gRow][k+0]=f2tf32(av.x); As[gRow][k+1]=f2tf32(av.y);
            As[gRow][k+2]=f2tf32(av.z); As[gRow][k+3]=f2tf32(av.w);
            Bs[gRow][k+0]=f2tf32(bv.x); Bs[gRow][k+1]=f2tf32(bv.y);
            Bs[gRow][k+2]=f2tf32(bv.z); Bs[gRow][k+3]=f2tf32(bv.w);
        }
        __syncthreads();
#pragma unroll
        for (int ks = 0; ks < 4; ks++) {
            const int k0 = ks * 8;
            uint32_t af[4][4], bf[4][2];
#pragma unroll
            for (int im = 0; im < 4; im++) {
                const int r = wm + im * 16 + lr;
                af[im][0]=As[r][k0+lc];   af[im][1]=As[r+8][k0+lc];
                af[im][2]=As[r][k0+lc+4]; af[im][3]=As[r+8][k0+lc+4];
            }
#pragma unroll
            for (int in = 0; in < 4; in++) {
                const int n = wn + in * 8 + lr;
                bf[in][0]=Bs[n][k0+lc]; bf[in][1]=Bs[n][k0+lc+4];
            }
#pragma unroll
            for (int im = 0; im < 4; im++)
#pragma unroll
                for (int in = 0; in < 4; in++)
                    mma_tf32(acc[im][in], af[im][0],af[im][1],af[im][2],af[im][3],
                             bf[in][0], bf[in][1]);
        }
        __syncthreads();
    }
#pragma unroll
    for (int im = 0; im < 4; im++) {
        const int r0 = m_blk + wm + im * 16 + lr;
#pragma unroll
        for (int in = 0; in < 4; in++) {
            const int c0 = n_blk + wn + in * 8 + 2 * lc;
            float2 bia = *(const float2*)&bias[c0];
            float x = acc[im][in].x + bia.x, y = acc[im][in].y + bia.y;
            float z = acc[im][in].z + bia.x, w = acc[im][in].w + bia.y;
            if (Ch) {
                const float s = (c0 < HID) ? SCALE : 1.f;
                x *= s; y *= s; z *= s; w *= s;
                const size_t w0 = (size_t)r0 * (N >> 1) + (c0 >> 1);
                const size_t w1 = (size_t)(r0 + 8) * (N >> 1) + (c0 >> 1);
                Ch[w0] = pack_hi(x, y); Cl[w0] = pack_lo(x, y);
                Ch[w1] = pack_hi(z, w); Cl[w1] = pack_lo(z, w);
            } else {
                float* Cp0 = C + (size_t)r0 * N + c0;
                float* Cp1 = C + (size_t)(r0 + 8) * N + c0;
                Cp0[0] = x; Cp0[1] = y; Cp1[0] = z; Cp1[1] = w;
            }
        }
    }
}

// ---------------- lambda scalar ----------------
__global__ void lambda_kernel(const float* __restrict__ q1, const float* __restrict__ k1,
                              const float* __restrict__ q2, const float* __restrict__ k2)
{
    const int tid = threadIdx.x;
    float p1 = q1[tid] * k1[tid];
    float p2 = q2[tid] * k2[tid];
#pragma unroll
    for (int m = 16; m; m >>= 1) {
        p1 += __shfl_xor_sync(0xffffffffu, p1, m);
        p2 += __shfl_xor_sync(0xffffffffu, p2, m);
    }
    __shared__ float s1[4], s2[4];
    if ((tid & 31) == 0) { s1[tid >> 5] = p1; s2[tid >> 5] = p2; }
    __syncthreads();
    if (tid == 0) {
        float a = s1[0]+s1[1]+s1[2]+s1[3];
        float b = s2[0]+s2[1]+s2[2]+s2[3];
        g_lambda = expf(a) - expf(b) + LAMBDA_INIT;
    }
}

// ---------------- bf16x3 flash attention, cp.async pipelined ----------------
#define QH_W 68
#define VH_W 132
#define PH_W 36
#define QH_OFF 0
#define QL_OFF (QH_OFF + 64*QH_W)
#define KH_OFF (QL_OFF + 64*QH_W)
#define KL_OFF (KH_OFF + 64*QH_W)
#define VH_OFF (KL_OFF + 64*QH_W)
#define VL_OFF (VH_OFF + 64*VH_W)
#define PH_OFF (VL_OFF + 64*VH_W)
#define PL_OFF (PH_OFF + 64*PH_W)
#define ST_OFF (PL_OFF + 64*PH_W)
#define ATT_WORDS (ST_OFF + 64*7)

__global__ __launch_bounds__(256, 1)
void diff_attn(const uint32_t* __restrict__ qh_g, const uint32_t* __restrict__ ql_g,
               float* __restrict__ out1, float* __restrict__ out2)
{
    extern __shared__ uint32_t sw[];
    float* mrow = (float*)(sw + ST_OFF);
    float* crow = mrow + 64;
    float* lrow = crow + 64;
    float* pmax = lrow + 64;      // [2][64]
    float* psum = pmax + 128;     // [2][64]

    const int tid = threadIdx.x, lane = tid & 31, w = tid >> 5;
    const int qi = gridDim.x - 1 - blockIdx.x;   // heavy blocks first
    const int hp = blockIdx.y, aa = blockIdx.z;
    const int q0 = qi * 64;
    const int qoffW = hp * 128 + aa * 64;
    const int koffW = 2048 + qoffW;
    const int voffW = 4096 + hp * 128;
    float* outp = aa ? out2 : out1;
    const uint32_t smb = (uint32_t)__cvta_generic_to_shared(sw);

    // --- prologue: Q + K(0) via cp.async ---
    {
        const int r = tid >> 2, c4 = (tid & 3) * 4;
#pragma unroll
        for (int i = 0; i < 4; i++) {
            const int ch = c4 + i;
            cpa16(smb + (QH_OFF + r * QH_W + ch * 4) * 4, qh_g + (size_t)(q0 + r) * NW + qoffW + ch * 4);
            cpa16(smb + (QL_OFF + r * QH_W + ch * 4) * 4, ql_g + (size_t)(q0 + r) * NW + qoffW + ch * 4);
            cpa16(smb + (KH_OFF + r * QH_W + ch * 4) * 4, qh_g + (size_t)r * NW + koffW + ch * 4);
            cpa16(smb + (KL_OFF + r * QH_W + ch * 4) * 4, ql_g + (size_t)r * NW + koffW + ch * 4);
        }
    }
    asm volatile("cp.async.commit_group;");
    if (tid < 64) { mrow[tid] = -1e30f; lrow[tid] = 0.f; }

    const int wm  = (w & 3) * 16;
    const int nh2 = w >> 2;
    const int wn  = nh2 * 32;
    const int en0 = nh2 * 128;
    const int lq  = lane >> 2;
    const int lr4 = lane & 3;

    float o[16][4];
#pragma unroll
    for (int i = 0; i < 16; i++)
#pragma unroll
        for (int j = 0; j < 4; j++) o[i][j] = 0.f;

    asm volatile("cp.async.wait_group 0;");
    __syncthreads();

    for (int t = 0; t <= qi; t++) {
        // --- issue V(t) loads (overlap with QK compute) ---
        {
            const int r = tid >> 2, cb = (tid & 3) * 8;
            const size_t gro = (size_t)(t * 64 + r) * NW + voffW;
#pragma unroll
            for (int i = 0; i < 8; i++) {
                const int ch = cb + i;
                cpa16(smb + (VH_OFF + r * VH_W + ch * 4) * 4, qh_g + gro + ch * 4);
                cpa16(smb + (VL_OFF + r * VH_W + ch * 4) * 4, ql_g + gro + ch * 4);
            }
        }
        asm volatile("cp.async.commit_group;");

        // --- S = Q K^T (warp: 16 rows x 32 cols), bf16x3 ---
        float c4[4][4];
#pragma unroll
        for (int nt = 0; nt < 4; nt++)
#pragma unroll
            for (int j = 0; j < 4; j++) c4[nt][j] = 0.f;

#pragma unroll
        for (int ks = 0; ks < 8; ks++) {
            const uint32_t cb = ks * 32 + (lane >> 4) * 16;
            uint32_t qh[4], ql[4];
            ldsm4(qh, smb + ((QH_OFF + (wm + (lane & 15)) * QH_W) << 2) + cb);
            ldsm4(ql, smb + ((QL_OFF + (wm + (lane & 15)) * QH_W) << 2) + cb);
#pragma unroll
            for (int nh = 0; nh < 2; nh++) {
                const int krow = wn + nh * 16 + (lane & 15);
                uint32_t kh[4], kl[4];
                ldsm4(kh, smb + ((KH_OFF + krow * QH_W) << 2) + cb);
                ldsm4(kl, smb + ((KL_OFF + krow * QH_W) << 2) + cb);
#pragma unroll
                for (int g = 0; g < 2; g++) {
                    float* c = c4[nh * 2 + g];
                    mma_bf16(c, qh[0],qh[1],qh[2],qh[3], kh[g], kh[g+2]);
                    mma_bf16(c, qh[0],qh[1],qh[2],qh[3], kl[g], kl[g+2]);
                    mma_bf16(c, ql[0],ql[1],ql[2],ql[3], kh[g], kh[g+2]);
                }
            }
        }

        // --- mask + row max ---
        const bool diag = (t == qi);
        float m0 = -1e30f, m1 = -1e30f;
#pragma unroll
        for (int nt = 0; nt < 4; nt++) {
            if (diag) {
                const int kc = wn + nt * 8 + 2 * lr4;
                const int rr0 = wm + lq, rr1 = rr0 + 8;
                if (kc     > rr0) c4[nt][0] = -1e30f;
                if (kc + 1 > rr0) c4[nt][1] = -1e30f;
                if (kc     > rr1) c4[nt][2] = -1e30f;
                if (kc + 1 > rr1) c4[nt][3] = -1e30f;
            }
            m0 = fmaxf(m0, fmaxf(c4[nt][0], c4[nt][1]));
            m1 = fmaxf(m1, fmaxf(c4[nt][2], c4[nt][3]));
        }
        m0 = fmaxf(m0, __shfl_xor_sync(0xffffffffu, m0, 1));
        m0 = fmaxf(m0, __shfl_xor_sync(0xffffffffu, m0, 2));
        m1 = fmaxf(m1, __shfl_xor_sync(0xffffffffu, m1, 1));
        m1 = fmaxf(m1, __shfl_xor_sync(0xffffffffu, m1, 2));
        if (lr4 == 0) {
            pmax[nh2 * 64 + wm + lq]     = m0;
            pmax[nh2 * 64 + wm + lq + 8] = m1;
        }
        __syncthreads();   // (b) pmax visible; all warps done with K buffer

        // --- issue K(t+1) loads (overlap with softmax + PV) ---
        if (t < qi) {
            const int r = tid >> 2, c4i = (tid & 3) * 4;
            const size_t gro = (size_t)((t + 1) * 64 + r) * NW + koffW;
#pragma unroll
            for (int i = 0; i < 4; i++) {
                const int ch = c4i + i;
                cpa16(smb + (KH_OFF + r * QH_W + ch * 4) * 4, qh_g + gro + ch * 4);
                cpa16(smb + (KL_OFF + r * QH_W + ch * 4) * 4, ql_g + gro + ch * 4);
            }
        }
        asm volatile("cp.async.commit_group;");   // (possibly empty group)

        if (tid < 64) {
            float mo = mrow[tid];
            float mn = fmaxf(mo, fmaxf(pmax[tid], pmax[64 + tid]));
            mrow[tid] = mn;
            crow[tid] = __expf(mo - mn);
        }
        __syncthreads();   // (c)

        // --- P = exp(S - m) -> smem, row sums, O rescale ---
        const float mn0 = mrow[wm + lq], mn1 = mrow[wm + lq + 8];
        const float cr0 = crow[wm + lq], cr1 = crow[wm + lq + 8];
        float s0 = 0.f, s1 = 0.f;
#pragma unroll
        for (int nt = 0; nt < 4; nt++) {
            float p0 = __expf(c4[nt][0] - mn0);
            float p1 = __expf(c4[nt][1] - mn0);
            float p2 = __expf(c4[nt][2] - mn1);
            float p3 = __expf(c4[nt][3] - mn1);
            s0 += p0 + p1; s1 += p2 + p3;
            const int wc = wn / 2 + nt * 4 + lr4;
            sw[PH_OFF + (wm + lq) * PH_W + wc]     = pack_hi(p0, p1);
            sw[PL_OFF + (wm + lq) * PH_W + wc]     = pack_lo(p0, p1);
            sw[PH_OFF + (wm + lq + 8) * PH_W + wc] = pack_hi(p2, p3);
            sw[PL_OFF + (wm + lq + 8) * PH_W + wc] = pack_lo(p2, p3);
        }
        s0 += __shfl_xor_sync(0xffffffffu, s0, 1);
        s0 += __shfl_xor_sync(0xffffffffu, s0, 2);
        s1 += __shfl_xor_sync(0xffffffffu, s1, 1);
        s1 += __shfl_xor_sync(0xffffffffu, s1, 2);
        if (lr4 == 0) {
            psum[nh2 * 64 + wm + lq]     = s0;
            psum[nh2 * 64 + wm + lq + 8] = s1;
        }
#pragma unroll
        for (int nt = 0; nt < 16; nt++) {
            o[nt][0] *= cr0; o[nt][1] *= cr0;
            o[nt][2] *= cr1; o[nt][3] *= cr1;
        }
        asm volatile("cp.async.wait_group 1;");   // V(t) complete (K(t+1) may still fly)
        __syncthreads();   // (d) P + V visible everywhere
        if (tid < 64) lrow[tid] = lrow[tid] * crow[tid] + psum[tid] + psum[64 + tid];

        // --- O += P V (warp: 16 rows x 128 e-cols), bf16x3 ---
#pragma unroll
        for (int ks = 0; ks < 4; ks++) {
            const uint32_t pcb = ks * 32 + (lane >> 4) * 16;
            uint32_t ph[4], pl[4];
            ldsm4(ph, smb + ((PH_OFF + (wm + (lane & 15)) * PH_W) << 2) + pcb);
            ldsm4(pl, smb + ((PL_OFF + (wm + (lane & 15)) * PH_W) << 2) + pcb);
            const int kvrow = ks * 16 + (lane & 15);
#pragma unroll
            for (int ec = 0; ec < 8; ec++) {
                const uint32_t vcb = (uint32_t)((en0 + ec * 16 + (lane >> 4) * 8) << 1);
                uint32_t vh[4], vl[4];
                ldsm4t(vh, smb + ((VH_OFF + kvrow * VH_W) << 2) + vcb);
                ldsm4t(vl, smb + ((VL_OFF + kvrow * VH_W) << 2) + vcb);
#pragma unroll
                for (int g = 0; g < 2; g++) {
                    float* oo = o[ec * 2 + g];
                    mma_bf16(oo, ph[0],ph[1],ph[2],ph[3], vh[2*g], vh[2*g+1]);
                    mma_bf16(oo, ph[0],ph[1],ph[2],ph[3], vl[2*g], vl[2*g+1]);
                    mma_bf16(oo, pl[0],pl[1],pl[2],pl[3], vh[2*g], vh[2*g+1]);
                }
            }
        }
        asm volatile("cp.async.wait_group 0;");   // K(t+1) complete
        __syncthreads();   // (e) protect K/V/P for next iteration
    }

    // --- epilogue ---
    const float inv0 = 1.f / lrow[wm + lq];
    const float inv1 = 1.f / lrow[wm + lq + 8];
    const size_t row0 = (size_t)q0 + wm + lq, row1 = row0 + 8;
#pragma unroll
    for (int nt = 0; nt < 16; nt++) {
        const int col = hp * 256 + en0 + nt * 8 + 2 * lr4;
        float2 v0 = make_float2(o[nt][0] * inv0, o[nt][1] * inv0);
        float2 v1 = make_float2(o[nt][2] * inv1, o[nt][3] * inv1);
        *(float2*)&outp[row0 * HID + col] = v0;
        *(float2*)&outp[row1 * HID + col] = v1;
    }
}

// ---------------- combine + RMSNorm ----------------
__global__ __launch_bounds__(256)
void combine_rms(const float* __restrict__ a1, const float* __restrict__ a2,
                 const float* __restrict__ w, float* __restrict__ x)
{
    const int s = blockIdx.x, hp = blockIdx.y, e = threadIdx.x;
    const size_t idx = (size_t)s * HID + hp * 256 + e;
    const float lam = g_lambda;
    const float v = a1[idx] - lam * a2[idx];
    float ss = v * v;
#pragma unroll
    for (int m = 16; m; m >>= 1) ss += __shfl_xor_sync(0xffffffffu, ss, m);
    __shared__ float red[8];
    if ((e & 31) == 0) red[e >> 5] = ss;
    __syncthreads();
    float tot = 0.f;
#pragma unroll
    for (int i = 0; i < 8; i++) tot += red[i];
    const float r = rsqrtf(tot * (1.f / 256.f) + EPS);
    x[idx] = w[e] * v * r * (1.f - LAMBDA_INIT);
}

// ---------------- launch ----------------
extern "C" void kernel_launch(void* const* d_in, const int* in_sizes, int n_in,
                              void* d_out, int out_size)
{
    const float* hidden = (const float*)d_in[0];
    const float* Wqkv_w = (const float*)d_in[1];
    const float* Wqkv_b = (const float*)d_in[2];
    const float* out_w  = (const float*)d_in[3];
    const float* out_b  = (const float*)d_in[4];
    const float* lq1    = (const float*)d_in[5];
    const float* lk1    = (const float*)d_in[6];
    const float* lq2    = (const float*)d_in[7];
    const float* lk2    = (const float*)d_in[8];
    const float* subln  = (const float*)d_in[9];
    float* out = (float*)d_out;

    uint32_t *qh, *ql;
    float *a1, *a2, *x;
    cudaGetSymbolAddress((void**)&qh, g_qkvh);
    cudaGetSymbolAddress((void**)&ql, g_qkvl);
    cudaGetSymbolAddress((void**)&a1, g_attn1);
    cudaGetSymbolAddress((void**)&a2, g_attn2);
    cudaGetSymbolAddress((void**)&x,  g_x);

    const int SMEM_ATT = ATT_WORDS * (int)sizeof(uint32_t);
    cudaFuncSetAttribute(diff_attn, cudaFuncAttributeMaxDynamicSharedMemorySize, SMEM_ATT);

    lambda_kernel<<<1, 128>>>(lq1, lk1, lq2, lk2);

    // QKV projection -> bf16 hi/lo split (Q pre-scaled)
    sgemm_tc<<<dim3(QKV_N / 128, S_LEN / 128), 256>>>(
        hidden, Wqkv_w, Wqkv_b, nullptr, qh, ql, S_LEN, QKV_N, HID);

    diff_attn<<<dim3(S_LEN / 64, HP_N, 2), 256, SMEM_ATT>>>(qh, ql, a1, a2);

    combine_rms<<<dim3(S_LEN, HP_N), 256>>>(a1, a2, subln, x);

    // output projection -> fp32
    sgemm_tc<<<dim3(HID / 128, S_LEN / 128), 256>>>(
        x, out_w, out_b, out, nullptr, nullptr, S_LEN, HID, HID);
}